// round 2
// baseline (speedup 1.0000x reference)
#include <cuda_runtime.h>
#include <cstdint>

#define BATCH 64
#define TT    2048
#define HID   128
#define G3    384
#define NPROD 84
#define NTHR  384

// Scratch: gi[t][b][g] (201 MB) + per-t ready flags. Device globals (no runtime alloc).
__device__ float g_gi[(size_t)TT * BATCH * G3];
__device__ int   g_flag[TT];

__device__ __forceinline__ unsigned long long pack2(float lo, float hi) {
    unsigned long long r;
    asm("mov.b64 %0, {%1, %2};" : "=l"(r) : "f"(lo), "f"(hi));
    return r;
}
__device__ __forceinline__ void unpack2(unsigned long long v, float &lo, float &hi) {
    asm("mov.b64 {%0, %1}, %2;" : "=f"(lo), "=f"(hi) : "l"(v));
}
// Packed f32x2 FMA: d = a*b + d (elementwise on 2 floats). 2x fp32 throughput on sm_103a.
__device__ __forceinline__ void ffma2(unsigned long long &d, unsigned long long a,
                                      unsigned long long b) {
    asm("fma.rn.f32x2 %0, %1, %2, %0;" : "+l"(d) : "l"(a), "l"(b));
}
__device__ __forceinline__ int ld_acquire(const int* p) {
    int v;
    asm volatile("ld.acquire.gpu.global.b32 %0, [%1];" : "=r"(v) : "l"(p));
    return v;
}
__device__ __forceinline__ void st_release(int* p, int v) {
    asm volatile("st.release.gpu.global.b32 [%0], %1;" :: "l"(p), "r"(v));
}
__device__ __forceinline__ float sigmoidf_(float x) {
    return __fdividef(1.0f, 1.0f + __expf(-x));
}

__global__ void reset_kernel() {
    int i = blockIdx.x * blockDim.x + threadIdx.x;
    if (i < TT) g_flag[i] = 0;
}

__global__ void __launch_bounds__(NTHR, 1)
gru_kernel(const float* __restrict__ x,      // [B, T, I=128]
           const float* __restrict__ w_ih,   // [384, 128]
           const float* __restrict__ w_hh,   // [384, 128]
           const float* __restrict__ b_ih,   // [384]
           const float* __restrict__ b_hh,   // [384]
           const float* __restrict__ w_proj, // [64, 128]
           const float* __restrict__ b_proj, // [64]
           float* __restrict__ out)          // [64, 64]
{
    __shared__ float s_x[BATCH * HID];   // producer staging: x[:, t, :]  (32 KB)
    __shared__ float s_h[HID];
    __shared__ float s_gh[G3];
    __shared__ float s_pool[HID];

    const int tid = threadIdx.x;

    if (blockIdx.x >= BATCH) {
        // ============================ PRODUCER ============================
        // Block (64+w) computes gi[t] for t = w, w+NPROD, ...  Thread g owns
        // w_ih row g in registers (64 f32x2), x[:,t,:] staged through smem
        // (broadcast reads), result published with a per-t release flag.
        const int w = blockIdx.x - BATCH;
        unsigned long long wr[64];
        const unsigned long long* W =
            reinterpret_cast<const unsigned long long*>(w_ih) + (size_t)tid * 64;
        #pragma unroll
        for (int i = 0; i < 64; i++) wr[i] = W[i];
        const unsigned long long bias = pack2(b_ih[tid], 0.0f);

        for (int t = w; t < TT; t += NPROD) {
            // stage x[:, t, :] -> smem (previous iter's readers are past the
            // publish barrier below, so writes are safe)
            for (int idx = tid; idx < BATCH * HID; idx += NTHR)
                s_x[idx] = x[(((size_t)(idx >> 7)) * TT + t) * HID + (idx & 127)];
            __syncthreads();

            float* gout = g_gi + (size_t)t * BATCH * G3;
            for (int b = 0; b < BATCH; b++) {
                const ulonglong2* hx = reinterpret_cast<const ulonglong2*>(s_x + b * HID);
                unsigned long long a0 = bias, a1 = pack2(0.0f, 0.0f);
                #pragma unroll
                for (int i = 0; i < 32; i++) {
                    ulonglong2 v = hx[i];
                    ffma2(a0, wr[2 * i],     v.x);
                    ffma2(a1, wr[2 * i + 1], v.y);
                }
                float s0, s1, s2, s3;
                unpack2(a0, s0, s1);
                unpack2(a1, s2, s3);
                gout[b * G3 + tid] = (s0 + s1) + (s2 + s3);
            }
            __threadfence();
            __syncthreads();
            if (tid == 0) st_release(&g_flag[t], 1);
        }
    } else {
        // ============================ CONSUMER ============================
        // Block b runs the full T=2048 recurrence for batch element b.
        // Thread g owns w_hh row g in registers; h lives in smem (broadcast).
        const int b = blockIdx.x;
        unsigned long long wr[64];
        const unsigned long long* W =
            reinterpret_cast<const unsigned long long*>(w_hh) + (size_t)tid * 64;
        #pragma unroll
        for (int i = 0; i < 64; i++) wr[i] = W[i];
        const unsigned long long bias = pack2(b_hh[tid], 0.0f);

        if (tid < HID) s_h[tid] = 0.0f;
        float pool = 0.0f;
        float h_j  = 0.0f;

        // wait for gi[0], prefetch it into registers
        while (!ld_acquire(&g_flag[0])) __nanosleep(32);
        const float* gi_b = g_gi + (size_t)b * G3;
        float gr = 0.0f, gz = 0.0f, gn = 0.0f;
        if (tid < HID) {
            gr = gi_b[tid];
            gz = gi_b[HID + tid];
            gn = gi_b[2 * HID + tid];
        }
        __syncthreads();

        for (int t = 0; t < TT; t++) {
            // issue next-step flag check early; result consumed after gates
            int fnext = 1;
            if (t + 1 < TT) fnext = ld_acquire(&g_flag[t + 1]);

            // ---- phase 1: gh[g] = w_hh[g,:] . h + b_hh[g] ----
            const ulonglong2* hp = reinterpret_cast<const ulonglong2*>(s_h);
            unsigned long long a0 = bias, a1 = pack2(0.0f, 0.0f);
            #pragma unroll
            for (int i = 0; i < 32; i++) {
                ulonglong2 v = hp[i];
                ffma2(a0, wr[2 * i],     v.x);
                ffma2(a1, wr[2 * i + 1], v.y);
            }
            float s0, s1, s2, s3;
            unpack2(a0, s0, s1);
            unpack2(a1, s2, s3);
            s_gh[tid] = (s0 + s1) + (s2 + s3);
            __syncthreads();

            // ---- phase 2: gates + h update (threads 0..127) ----
            if (tid < HID) {
                float r = sigmoidf_(gr + s_gh[tid]);
                float z = sigmoidf_(gz + s_gh[HID + tid]);
                float c = gn + r * s_gh[2 * HID + tid];
                float n = 2.0f * sigmoidf_(2.0f * c) - 1.0f;  // tanh(c)
                h_j = n + z * (h_j - n);
                pool += h_j;
                s_h[tid] = h_j;
            }
            __syncthreads();

            // ---- prefetch gi[t+1] (hidden under next GEMV) ----
            if (t + 1 < TT) {
                while (!fnext) { fnext = ld_acquire(&g_flag[t + 1]); }
                if (tid < HID) {
                    const float* p = gi_b + (size_t)(t + 1) * BATCH * G3;
                    gr = p[tid];
                    gz = p[HID + tid];
                    gn = p[2 * HID + tid];
                }
            }
        }

        // ---- mean pool + projection ----
        if (tid < HID) s_pool[tid] = pool * (1.0f / (float)TT);
        __syncthreads();
        if (tid < 64) {
            float acc = b_proj[tid];
            const float* wp = w_proj + tid * HID;
            #pragma unroll 8
            for (int j = 0; j < HID; j++) acc += wp[j] * s_pool[j];
            out[b * 64 + tid] = acc;
        }
    }
}

extern "C" void kernel_launch(void* const* d_in, const int* in_sizes, int n_in,
                              void* d_out, int out_size) {
    const float* x      = (const float*)d_in[0];
    const float* w_ih   = (const float*)d_in[1];
    const float* w_hh   = (const float*)d_in[2];
    const float* b_ih   = (const float*)d_in[3];
    const float* b_hh   = (const float*)d_in[4];
    const float* w_proj = (const float*)d_in[5];
    const float* b_proj = (const float*)d_in[6];
    float* out = (float*)d_out;

    reset_kernel<<<(TT + 255) / 256, 256>>>();
    gru_kernel<<<BATCH + NPROD, NTHR>>>(x, w_ih, w_hh, b_ih, b_hh, w_proj, b_proj, out);
}

// round 5
// speedup vs baseline: 1.2473x; 1.2473x over previous
#include <cuda_runtime.h>
#include <cstdint>

#define BATCH 64
#define TT    2048
#define HID   128
#define G3    384
#define NPROD 84
#define NTHR  384
#define NCH   ((TT + NPROD - 1) / NPROD)   // 25 chunks

// Scratch: gi[t][b][g] (201 MB) + per-chunk completion counters. Device globals.
__device__ float g_gi[(size_t)TT * BATCH * G3];
__device__ int   g_cnt[NCH];

__device__ __forceinline__ unsigned long long pack2(float lo, float hi) {
    unsigned long long r;
    asm("mov.b64 %0, {%1, %2};" : "=l"(r) : "f"(lo), "f"(hi));
    return r;
}
__device__ __forceinline__ void unpack2(unsigned long long v, float &lo, float &hi) {
    asm("mov.b64 {%0, %1}, %2;" : "=f"(lo), "=f"(hi) : "l"(v));
}
// Packed f32x2 FMA: d = a*b + d (2 fp32 MACs/lane). 2x fp32 throughput on sm_103a.
__device__ __forceinline__ void ffma2(unsigned long long &d, unsigned long long a,
                                      unsigned long long b) {
    asm("fma.rn.f32x2 %0, %1, %2, %0;" : "+l"(d) : "l"(a), "l"(b));
}
__device__ __forceinline__ float sigmoidf_(float x) {
    return __fdividef(1.0f, 1.0f + __expf(-x));
}

// Consumer-side wait: every thread spins on a volatile read of the chunk
// counter, then executes its own __threadfence() (acquire side, pairing with
// the producer's release-side fence through the observed atomic).
__device__ __forceinline__ void wait_chunk(int c, int target) {
    volatile int* p = (volatile int*)&g_cnt[c];
    while (*p < target) __nanosleep(64);
    __threadfence();
}

__global__ void reset_kernel() {
    int i = threadIdx.x;
    if (i < NCH) g_cnt[i] = 0;
}

__global__ void __launch_bounds__(NTHR, 1)
gru_kernel(const float* __restrict__ x,      // [B, T, I=128]
           const float* __restrict__ w_ih,   // [384, 128]
           const float* __restrict__ w_hh,   // [384, 128]
           const float* __restrict__ b_ih,   // [384]
           const float* __restrict__ b_hh,   // [384]
           const float* __restrict__ w_proj, // [64, 128]
           const float* __restrict__ b_proj, // [64]
           float* __restrict__ out)          // [64, 64]
{
    __shared__ float s_x[BATCH * HID];   // producer staging (32 KB)
    __shared__ float s_h[HID];
    __shared__ float s_gh[G3];
    __shared__ float s_pool[HID];

    const int tid = threadIdx.x;

    if (blockIdx.x >= BATCH) {
        // ============================ PRODUCER ============================
        // Round c: block (64+w) computes gi[t] for t = c*NPROD + w, then
        // (after a release-side fence) atomically bumps g_cnt[c].
        const int w = blockIdx.x - BATCH;
        unsigned long long wr[64];
        const unsigned long long* W =
            reinterpret_cast<const unsigned long long*>(w_ih) + (size_t)tid * 64;
        #pragma unroll
        for (int i = 0; i < 64; i++) wr[i] = W[i];
        const unsigned long long bias = pack2(b_ih[tid], 0.0f);

        for (int c = 0; c < NCH; c++) {
            const int t = c * NPROD + w;
            if (t >= TT) break;
            // stage x[:, t, :] -> smem
            for (int idx = tid; idx < BATCH * HID; idx += NTHR)
                s_x[idx] = __ldcg(&x[(((size_t)(idx >> 7)) * TT + t) * HID + (idx & 127)]);
            __syncthreads();

            float* gout = g_gi + (size_t)t * BATCH * G3;
            for (int b = 0; b < BATCH; b++) {
                const ulonglong2* hx = reinterpret_cast<const ulonglong2*>(s_x + b * HID);
                unsigned long long a0 = bias, a1 = pack2(0.0f, 0.0f);
                #pragma unroll
                for (int i = 0; i < 32; i++) {
                    ulonglong2 v = hx[i];
                    ffma2(a0, wr[2 * i],     v.x);
                    ffma2(a1, wr[2 * i + 1], v.y);
                }
                float s0, s1, s2, s3;
                unpack2(a0, s0, s1);
                unpack2(a1, s2, s3);
                gout[b * G3 + tid] = (s0 + s1) + (s2 + s3);
            }
            __threadfence();            // release side: order gi stores @gpu scope
            __syncthreads();            // all 384 threads' stores fenced before publish
            if (tid == 0) atomicAdd(&g_cnt[c], 1);
            __syncthreads();            // protect s_x for next round
        }
    } else {
        // ============================ CONSUMER ============================
        // Block b runs the full T=2048 recurrence for batch element b.
        const int b = blockIdx.x;
        unsigned long long wr[64];
        const unsigned long long* W =
            reinterpret_cast<const unsigned long long*>(w_hh) + (size_t)tid * 64;
        #pragma unroll
        for (int i = 0; i < 64; i++) wr[i] = W[i];
        const unsigned long long bias = pack2(b_hh[tid], 0.0f);

        if (tid < HID) s_h[tid] = 0.0f;
        float pool = 0.0f;
        float h_j  = 0.0f;

        const float* gi_b = g_gi + (size_t)b * G3;

        // wait for chunk 0 (all threads), then load gi[0]
        wait_chunk(0, NPROD);
        float gr = 0.0f, gz = 0.0f, gn = 0.0f;   // current step's gi
        float pr = 0.0f, pz = 0.0f, pn = 0.0f;   // prefetched next step
        if (tid < HID) {
            gr = __ldcg(gi_b + tid);
            gz = __ldcg(gi_b + HID + tid);
            gn = __ldcg(gi_b + 2 * HID + tid);
        }
        __syncthreads();

        int tin = 0;     // index of t within current chunk
        int c   = 0;     // current chunk

        for (int t = 0; t < TT; t++) {
            const bool have_next = (t + 1 < TT);
            const bool boundary  = (tin + 1 == NPROD);   // t+1 opens a new chunk

            // prefetch gi[t+1] early (same chunk -> already published & fenced)
            if (have_next && !boundary && tid < HID) {
                const float* p = gi_b + (size_t)(t + 1) * BATCH * G3;
                pr = __ldcg(p + tid);
                pz = __ldcg(p + HID + tid);
                pn = __ldcg(p + 2 * HID + tid);
            }

            // ---- phase 1: gh[g] = w_hh[g,:] . h + b_hh[g] ----
            const ulonglong2* hp = reinterpret_cast<const ulonglong2*>(s_h);
            unsigned long long a0 = bias, a1 = pack2(0.0f, 0.0f);
            #pragma unroll
            for (int i = 0; i < 32; i++) {
                ulonglong2 v = hp[i];
                ffma2(a0, wr[2 * i],     v.x);
                ffma2(a1, wr[2 * i + 1], v.y);
            }
            float s0, s1, s2, s3;
            unpack2(a0, s0, s1);
            unpack2(a1, s2, s3);
            s_gh[tid] = (s0 + s1) + (s2 + s3);
            __syncthreads();

            // ---- phase 2: gates + h update (threads 0..127) ----
            if (tid < HID) {
                float r = sigmoidf_(gr + s_gh[tid]);
                float z = sigmoidf_(gz + s_gh[HID + tid]);
                float cc = gn + r * s_gh[2 * HID + tid];
                float n = 2.0f * sigmoidf_(2.0f * cc) - 1.0f;  // tanh(cc)
                h_j = n + z * (h_j - n);
                pool += h_j;
                s_h[tid] = h_j;
            }
            __syncthreads();

            if (have_next) {
                if (boundary) {
                    c++; tin = 0;
                    const int target = (TT - c * NPROD < NPROD) ? (TT - c * NPROD) : NPROD;
                    wait_chunk(c, target);          // all threads; own fence each
                    if (tid < HID) {
                        const float* p = gi_b + (size_t)(t + 1) * BATCH * G3;
                        gr = __ldcg(p + tid);
                        gz = __ldcg(p + HID + tid);
                        gn = __ldcg(p + 2 * HID + tid);
                    }
                } else {
                    tin++;
                    gr = pr; gz = pz; gn = pn;
                }
            }
        }

        // ---- mean pool + projection ----
        if (tid < HID) s_pool[tid] = pool * (1.0f / (float)TT);
        __syncthreads();
        if (tid < 64) {
            float acc = b_proj[tid];
            const float* wp = w_proj + tid * HID;
            #pragma unroll 8
            for (int j = 0; j < HID; j++) acc += wp[j] * s_pool[j];
            out[b * 64 + tid] = acc;
        }
    }
}

extern "C" void kernel_launch(void* const* d_in, const int* in_sizes, int n_in,
                              void* d_out, int out_size) {
    const float* x      = (const float*)d_in[0];
    const float* w_ih   = (const float*)d_in[1];
    const float* w_hh   = (const float*)d_in[2];
    const float* b_ih   = (const float*)d_in[3];
    const float* b_hh   = (const float*)d_in[4];
    const float* w_proj = (const float*)d_in[5];
    const float* b_proj = (const float*)d_in[6];
    float* out = (float*)d_out;

    reset_kernel<<<1, 32>>>();
    gru_kernel<<<BATCH + NPROD, NTHR>>>(x, w_ih, w_hh, b_ih, b_hh, w_proj, b_proj, out);
}